// round 15
// baseline (speedup 1.0000x reference)
#include <cuda_runtime.h>
#include <cuda_fp16.h>
#include <cstdint>

#define BATCH 4
#define CIN   256
#define NPTS  4096
#define OUTC  256
// Q is pre-scaled by SCALE * log2(e) so softmax can use ex2 directly.
#define QSCALE (0.0625f * 1.44269504f)
#define NT    64        // key tiles of 64

__device__ __align__(16) __half g_qh[BATCH * NPTS * OUTC];
__device__ __align__(16) __half g_kh[BATCH * NPTS * OUTC];
__device__ __align__(16) __half g_vt[BATCH * OUTC * NPTS];

// ---------------------------------------------------------------------------
// MMA / ldmatrix helpers
// ---------------------------------------------------------------------------
__device__ __forceinline__ void ldsm_x4(unsigned& r0, unsigned& r1,
                                        unsigned& r2, unsigned& r3, unsigned addr)
{
    asm volatile("ldmatrix.sync.aligned.m8n8.x4.shared.b16 {%0,%1,%2,%3}, [%4];"
                 : "=r"(r0), "=r"(r1), "=r"(r2), "=r"(r3) : "r"(addr));
}
__device__ __forceinline__ void ldsm_x4_t(unsigned& r0, unsigned& r1,
                                          unsigned& r2, unsigned& r3, unsigned addr)
{
    asm volatile("ldmatrix.sync.aligned.m8n8.x4.trans.shared.b16 {%0,%1,%2,%3}, [%4];"
                 : "=r"(r0), "=r"(r1), "=r"(r2), "=r"(r3) : "r"(addr));
}
__device__ __forceinline__ void mma16816(float4& d,
    unsigned a0, unsigned a1, unsigned a2, unsigned a3, unsigned b0, unsigned b1)
{
    asm volatile(
        "mma.sync.aligned.m16n8k16.row.col.f32.f16.f16.f32 "
        "{%0,%1,%2,%3}, {%4,%5,%6,%7}, {%8,%9}, {%0,%1,%2,%3};"
        : "+f"(d.x), "+f"(d.y), "+f"(d.z), "+f"(d.w)
        : "r"(a0), "r"(a1), "r"(a2), "r"(a3), "r"(b0), "r"(b1));
}
__device__ __forceinline__ unsigned pack_f16x2(float e0, float e1) {
    unsigned u;
    asm("cvt.rn.f16x2.f32 %0, %1, %2;" : "=r"(u) : "f"(e1), "f"(e0));
    return u;
}
__device__ __forceinline__ float ex2(float x) {
    float r;
    asm("ex2.approx.f32 %0, %1;" : "=f"(r) : "f"(x));
    return r;
}
__device__ __forceinline__ void cp16(unsigned dst, const void* src) {
    asm volatile("cp.async.cg.shared.global [%0], [%1], 16;" :: "r"(dst), "l"(src));
}

// ---------------------------------------------------------------------------
// Projection on tensor cores (Q scale now QSCALE; otherwise unchanged, ~4us)
// ---------------------------------------------------------------------------
__global__ __launch_bounds__(256) void proj_mma_kernel(
    const float* __restrict__ x, const float* __restrict__ xx,
    const float* __restrict__ Wq, const float* __restrict__ Wk,
    const float* __restrict__ Wv)
{
    __shared__ __align__(16) char sm[128 * 72 * 2 + 64 * 136 * 2];
    __half* As = (__half*)sm;
    __half* Bs = (__half*)(sm + 128 * 72 * 2);
    __half* St = (__half*)sm;

    const int which = blockIdx.z / BATCH;
    const int b     = blockIdx.z % BATCH;
    const float* __restrict__ in = (which == 0) ? x : xx;
    const float* __restrict__ W  = (which == 0) ? Wq : ((which == 1) ? Wk : Wv);

    const int n0   = blockIdx.x * 128;
    const int o0   = blockIdx.y * 128;
    const int tid  = threadIdx.x;
    const int lane = tid & 31;
    const int warp = tid >> 5;
    const int g    = lane >> 2;
    const int tq   = lane & 3;
    const int wr   = warp >> 1;
    const int wcn  = warp & 1;

    const unsigned ab = (unsigned)__cvta_generic_to_shared(As);
    const unsigned bb = (unsigned)__cvta_generic_to_shared(Bs);

    float4 acc[2][8];
    #pragma unroll
    for (int mt = 0; mt < 2; mt++)
        #pragma unroll
        for (int j = 0; j < 8; j++) acc[mt][j] = make_float4(0.f, 0.f, 0.f, 0.f);

    for (int c0 = 0; c0 < CIN; c0 += 64) {
        __syncthreads();
        for (int t = tid; t < 128 * 16; t += 256) {
            int r = t >> 4, cc = (t & 15) * 4;
            float4 w = *(const float4*)&W[(o0 + r) * CIN + c0 + cc];
            half2* d = (half2*)&As[r * 72 + cc];
            d[0] = __floats2half2_rn(w.x, w.y);
            d[1] = __floats2half2_rn(w.z, w.w);
        }
        for (int t = tid; t < 64 * 32; t += 256) {
            int r = t >> 5, nn = (t & 31) * 4;
            float4 v = *(const float4*)&in[((size_t)b * CIN + c0 + r) * NPTS + n0 + nn];
            half2* d = (half2*)&Bs[r * 136 + nn];
            d[0] = __floats2half2_rn(v.x, v.y);
            d[1] = __floats2half2_rn(v.z, v.w);
        }
        __syncthreads();

        #pragma unroll
        for (int s = 0; s < 4; s++) {
            unsigned a[2][4];
            #pragma unroll
            for (int mt = 0; mt < 2; mt++)
                ldsm_x4(a[mt][0], a[mt][1], a[mt][2], a[mt][3],
                        ab + ((32 * wr + 16 * mt + (lane & 15)) * 72
                              + (lane >> 4) * 8 + 16 * s) * 2);
            #pragma unroll
            for (int ntp = 0; ntp < 4; ntp++) {
                unsigned b0, b1, b2, b3;
                ldsm_x4_t(b0, b1, b2, b3,
                          bb + ((16 * s + (lane & 15)) * 136
                                + 64 * wcn + 16 * ntp + 8 * (lane >> 4)) * 2);
                #pragma unroll
                for (int mt = 0; mt < 2; mt++) {
                    mma16816(acc[mt][2 * ntp],     a[mt][0], a[mt][1], a[mt][2], a[mt][3], b0, b1);
                    mma16816(acc[mt][2 * ntp + 1], a[mt][0], a[mt][1], a[mt][2], a[mt][3], b2, b3);
                }
            }
        }
    }
    __syncthreads();

    if (which == 2) {
        #pragma unroll
        for (int mt = 0; mt < 2; mt++)
            #pragma unroll
            for (int j = 0; j < 8; j++) {
                int o_ = 32 * wr + 16 * mt + g;
                int n_ = 64 * wcn + 8 * j + 2 * tq;
                *(half2*)&St[o_ * 136 + n_]       = __floats2half2_rn(acc[mt][j].x, acc[mt][j].y);
                *(half2*)&St[(o_ + 8) * 136 + n_] = __floats2half2_rn(acc[mt][j].z, acc[mt][j].w);
            }
        __syncthreads();
        for (int t = tid; t < 128 * 16; t += 256) {
            int r = t >> 4, nn = (t & 15) * 8;
            *(uint4*)&g_vt[((size_t)b * OUTC + o0 + r) * NPTS + n0 + nn] =
                *(uint4*)&St[r * 136 + nn];
        }
    } else {
        const float sc = (which == 0) ? QSCALE : 1.0f;
        __half* base = (which == 0) ? g_qh : g_kh;
        #pragma unroll
        for (int mt = 0; mt < 2; mt++)
            #pragma unroll
            for (int j = 0; j < 8; j++) {
                int o_ = 32 * wr + 16 * mt + g;
                int n_ = 64 * wcn + 8 * j + 2 * tq;
                St[n_ * 136 + o_]           = __float2half_rn(acc[mt][j].x * sc);
                St[(n_ + 1) * 136 + o_]     = __float2half_rn(acc[mt][j].y * sc);
                St[n_ * 136 + o_ + 8]       = __float2half_rn(acc[mt][j].z * sc);
                St[(n_ + 1) * 136 + o_ + 8] = __float2half_rn(acc[mt][j].w * sc);
            }
        __syncthreads();
        for (int t = tid; t < 128 * 16; t += 256) {
            int r = t >> 4, oc = (t & 15) * 8;
            *(uint4*)&base[((size_t)(b * NPTS) + n0 + r) * OUTC + o0 + oc] =
                *(uint4*)&St[r * 136 + oc];
        }
    }
}

// ---------------------------------------------------------------------------
// Flash attention v5: v4 + ex2 softmax, exp/PV interleave, deferred l-reduce,
// coalesced epilogue through smem.
// BM=128 queries/CTA, 8 warps (16 rows each, all 64 keys), grid 32x4 = 128 CTAs.
// ---------------------------------------------------------------------------
struct AttnSmem5 {
    __half Qs[128 * 264];     // 67584 B
    __half Ks[2][64 * 264];   // 2 x 33792 B
    __half Vs[2][256 * 72];   // 2 x 36864 B
};                            // 208896 B -> 1 CTA/SM
// Epilogue overlays a float O[256][132] (135168 B) on this region.

__global__ __launch_bounds__(256, 1) void attn_kernel5(float* __restrict__ out)
{
    extern __shared__ char smraw[];
    AttnSmem5& S = *reinterpret_cast<AttnSmem5*>(smraw);

    const int tid  = threadIdx.x;
    const int lane = tid & 31;
    const int w    = tid >> 5;
    const int g    = lane >> 2;
    const int tq   = lane & 3;
    const int b    = blockIdx.y;
    const int n0   = blockIdx.x * 128;

    const __half* __restrict__ Qh = g_qh + (size_t)b * NPTS * OUTC;
    const __half* __restrict__ Kh = g_kh + (size_t)b * NPTS * OUTC;
    const __half* __restrict__ Vt = g_vt + (size_t)b * OUTC * NPTS;

    const unsigned qb = (unsigned)__cvta_generic_to_shared(S.Qs);
    const unsigned kb = (unsigned)__cvta_generic_to_shared(S.Ks[0]);
    const unsigned vb = (unsigned)__cvta_generic_to_shared(S.Vs[0]);

    // ---- prologue: cp.async Q (persistent) + K/V tile 0 ----
    #pragma unroll
    for (int i = 0; i < 16; i++) {
        int idx = tid + i * 256;
        int r = idx >> 5, c = idx & 31;
        cp16(qb + (r * 264 + c * 8) * 2, &Qh[(size_t)(n0 + r) * OUTC + c * 8]);
    }
    #pragma unroll
    for (int i = 0; i < 8; i++) {
        int idx = tid + i * 256;
        int r = idx >> 5, c = idx & 31;
        cp16(kb + (r * 264 + c * 8) * 2, &Kh[(size_t)r * OUTC + c * 8]);
        int d = idx >> 3, c2 = idx & 7;
        cp16(vb + (d * 72 + c2 * 8) * 2, &Vt[(size_t)d * NPTS + c2 * 8]);
    }
    asm volatile("cp.async.commit_group;" ::: "memory");

    const unsigned aQ  = qb + ((16 * w + (lane & 15)) * 264 + (lane >> 4) * 8) * 2;
    const unsigned bK0 = kb + (((lane & 7) + 8 * (lane >> 4)) * 264
                               + ((lane >> 3) & 1) * 8) * 2;
    const unsigned bV0 = vb + (((lane & 7) + 8 * (lane >> 4)) * 72
                               + ((lane >> 3) & 1) * 8) * 2;

    float l0 = 0.f, l1 = 0.f;        // per-thread partials; lane-reduced at end
    float4 oacc[32];
    #pragma unroll
    for (int i = 0; i < 32; i++) oacc[i] = make_float4(0.f, 0.f, 0.f, 0.f);

    for (int t = 0; t < NT; t++) {
        const int buf = t & 1;

        asm volatile("cp.async.wait_group 0;" ::: "memory");
        __syncthreads();

        if (t + 1 < NT) {
            const int k0n = (t + 1) * 64;
            const unsigned kN = kb + (buf ^ 1) * (64 * 264 * 2);
            const unsigned vN = vb + (buf ^ 1) * (256 * 72 * 2);
            #pragma unroll
            for (int i = 0; i < 8; i++) {
                int idx = tid + i * 256;
                int r = idx >> 5, c = idx & 31;
                cp16(kN + (r * 264 + c * 8) * 2,
                     &Kh[(size_t)(k0n + r) * OUTC + c * 8]);
                int d = idx >> 3, c2 = idx & 7;
                cp16(vN + (d * 72 + c2 * 8) * 2,
                     &Vt[(size_t)d * NPTS + k0n + c2 * 8]);
            }
        }
        asm volatile("cp.async.commit_group;" ::: "memory");

        // ---- S = Q K^T : warp computes 16 rows x 64 keys ----
        float4 sacc[8];
        #pragma unroll
        for (int nt = 0; nt < 8; nt++) sacc[nt] = make_float4(0.f, 0.f, 0.f, 0.f);

        const unsigned kB = bK0 + buf * (64 * 264 * 2);
        #pragma unroll
        for (int s = 0; s < 16; s++) {
            unsigned a0, a1, a2, a3;
            ldsm_x4(a0, a1, a2, a3, aQ + s * 32);
            #pragma unroll
            for (int kt = 0; kt < 4; kt++) {
                unsigned b0, b1, b2, b3;
                ldsm_x4(b0, b1, b2, b3, kB + kt * 8448 + s * 32);
                mma16816(sacc[2 * kt],     a0, a1, a2, a3, b0, b1);
                mma16816(sacc[2 * kt + 1], a0, a1, a2, a3, b2, b3);
            }
        }

        const unsigned vB = bV0 + buf * (256 * 72 * 2);
        unsigned pa[16];

        // ---- exp (keys 0-31): S already includes log2(e) factor -> ex2 ----
        #pragma unroll
        for (int s = 0; s < 2; s++) {
            float x0 = ex2(sacc[2 * s].x),     y0 = ex2(sacc[2 * s].y);
            float z0 = ex2(sacc[2 * s].z),     w0 = ex2(sacc[2 * s].w);
            float x1 = ex2(sacc[2 * s + 1].x), y1 = ex2(sacc[2 * s + 1].y);
            float z1 = ex2(sacc[2 * s + 1].z), w1 = ex2(sacc[2 * s + 1].w);
            l0 += x0 + y0 + x1 + y1;
            l1 += z0 + w0 + z1 + w1;
            pa[4 * s + 0] = pack_f16x2(x0, y0);
            pa[4 * s + 1] = pack_f16x2(z0, w0);
            pa[4 * s + 2] = pack_f16x2(x1, y1);
            pa[4 * s + 3] = pack_f16x2(z1, w1);
        }

        // ---- PV step 0 (keys 0-15) — overlaps exp of keys 32-63 below ----
        #pragma unroll
        for (int vt = 0; vt < 16; vt++) {
            unsigned b0, b1, b2, b3;
            ldsm_x4(b0, b1, b2, b3, vB + vt * 2304);
            mma16816(oacc[2 * vt],     pa[0], pa[1], pa[2], pa[3], b0, b1);
            mma16816(oacc[2 * vt + 1], pa[0], pa[1], pa[2], pa[3], b2, b3);
        }

        // ---- exp (keys 32-63) ----
        #pragma unroll
        for (int s = 2; s < 4; s++) {
            float x0 = ex2(sacc[2 * s].x),     y0 = ex2(sacc[2 * s].y);
            float z0 = ex2(sacc[2 * s].z),     w0 = ex2(sacc[2 * s].w);
            float x1 = ex2(sacc[2 * s + 1].x), y1 = ex2(sacc[2 * s + 1].y);
            float z1 = ex2(sacc[2 * s + 1].z), w1 = ex2(sacc[2 * s + 1].w);
            l0 += x0 + y0 + x1 + y1;
            l1 += z0 + w0 + z1 + w1;
            pa[4 * s + 0] = pack_f16x2(x0, y0);
            pa[4 * s + 1] = pack_f16x2(z0, w0);
            pa[4 * s + 2] = pack_f16x2(x1, y1);
            pa[4 * s + 3] = pack_f16x2(z1, w1);
        }

        // ---- PV steps 1-3 ----
        #pragma unroll
        for (int s = 1; s < 4; s++) {
            #pragma unroll
            for (int vt = 0; vt < 16; vt++) {
                unsigned b0, b1, b2, b3;
                ldsm_x4(b0, b1, b2, b3, vB + vt * 2304 + s * 32);
                mma16816(oacc[2 * vt],     pa[4 * s], pa[4 * s + 1], pa[4 * s + 2], pa[4 * s + 3], b0, b1);
                mma16816(oacc[2 * vt + 1], pa[4 * s], pa[4 * s + 1], pa[4 * s + 2], pa[4 * s + 3], b2, b3);
            }
        }
    }

    // ---- lane-reduce l (tq group of 4 shares a row) ----
    #pragma unroll
    for (int mk = 1; mk <= 2; mk <<= 1) {
        l0 += __shfl_xor_sync(0xffffffffu, l0, mk);
        l1 += __shfl_xor_sync(0xffffffffu, l1, mk);
    }
    const float inv0 = 1.0f / l0;
    const float inv1 = 1.0f / l1;

    // ---- epilogue: stage O in smem as [col][n] (stride 132), then float4 STG ----
    float* Osm = (float*)smraw;
    __syncthreads();   // all smem reads of last tile done
    {
        const int rA = 16 * w + g;
        const int rB = rA + 8;
        #pragma unroll
        for (int dt = 0; dt < 32; dt++) {
            int col = 8 * dt + 2 * tq;
            Osm[(col)     * 132 + rA] = oacc[dt].x * inv0;
            Osm[(col + 1) * 132 + rA] = oacc[dt].y * inv0;
            Osm[(col)     * 132 + rB] = oacc[dt].z * inv1;
            Osm[(col + 1) * 132 + rB] = oacc[dt].w * inv1;
        }
    }
    __syncthreads();
    #pragma unroll
    for (int cc = 0; cc < 32; cc++) {
        int col = cc * 8 + w;
        int n = 4 * lane;
        float4 v = *(float4*)&Osm[col * 132 + n];
        *(float4*)&out[((size_t)b * OUTC + col) * NPTS + n0 + n] = v;
    }
}

// ---------------------------------------------------------------------------
extern "C" void kernel_launch(void* const* d_in, const int* in_sizes, int n_in,
                              void* d_out, int out_size)
{
    const float* x  = (const float*)d_in[0];
    const float* xx = (const float*)d_in[1];
    const float* Wq = (const float*)d_in[2];
    const float* Wk = (const float*)d_in[3];
    const float* Wv = (const float*)d_in[4];
    float* out = (float*)d_out;

    cudaFuncSetAttribute(attn_kernel5, cudaFuncAttributeMaxDynamicSharedMemorySize,
                         (int)sizeof(AttnSmem5));

    proj_mma_kernel<<<dim3(NPTS / 128, OUTC / 128, 3 * BATCH), 256>>>(x, xx, Wq, Wk, Wv);
    attn_kernel5<<<dim3(NPTS / 128, BATCH), 256, sizeof(AttnSmem5)>>>(out);
}

// round 16
// speedup vs baseline: 1.2066x; 1.2066x over previous
#include <cuda_runtime.h>
#include <cuda_fp16.h>
#include <cstdint>

#define BATCH 4
#define CIN   256
#define NPTS  4096
#define OUTC  256
// Q is pre-scaled by SCALE * log2(e) so softmax can use ex2 directly.
#define QSCALE (0.0625f * 1.44269504f)
#define NT    64        // key tiles of 64

__device__ __align__(16) __half g_qh[BATCH * NPTS * OUTC];
__device__ __align__(16) __half g_kh[BATCH * NPTS * OUTC];
__device__ __align__(16) __half g_vt[BATCH * OUTC * NPTS];

// ---------------------------------------------------------------------------
// MMA / ldmatrix / mbarrier helpers
// ---------------------------------------------------------------------------
__device__ __forceinline__ void ldsm_x4(unsigned& r0, unsigned& r1,
                                        unsigned& r2, unsigned& r3, unsigned addr)
{
    asm volatile("ldmatrix.sync.aligned.m8n8.x4.shared.b16 {%0,%1,%2,%3}, [%4];"
                 : "=r"(r0), "=r"(r1), "=r"(r2), "=r"(r3) : "r"(addr));
}
__device__ __forceinline__ void ldsm_x4_t(unsigned& r0, unsigned& r1,
                                          unsigned& r2, unsigned& r3, unsigned addr)
{
    asm volatile("ldmatrix.sync.aligned.m8n8.x4.trans.shared.b16 {%0,%1,%2,%3}, [%4];"
                 : "=r"(r0), "=r"(r1), "=r"(r2), "=r"(r3) : "r"(addr));
}
__device__ __forceinline__ void mma16816(float4& d,
    unsigned a0, unsigned a1, unsigned a2, unsigned a3, unsigned b0, unsigned b1)
{
    asm volatile(
        "mma.sync.aligned.m16n8k16.row.col.f32.f16.f16.f32 "
        "{%0,%1,%2,%3}, {%4,%5,%6,%7}, {%8,%9}, {%0,%1,%2,%3};"
        : "+f"(d.x), "+f"(d.y), "+f"(d.z), "+f"(d.w)
        : "r"(a0), "r"(a1), "r"(a2), "r"(a3), "r"(b0), "r"(b1));
}
__device__ __forceinline__ unsigned pack_f16x2(float e0, float e1) {
    unsigned u;
    asm("cvt.rn.f16x2.f32 %0, %1, %2;" : "=r"(u) : "f"(e1), "f"(e0));
    return u;
}
__device__ __forceinline__ float ex2(float x) {
    float r;
    asm("ex2.approx.f32 %0, %1;" : "=f"(r) : "f"(x));
    return r;
}
__device__ __forceinline__ void cp16(unsigned dst, const void* src) {
    asm volatile("cp.async.cg.shared.global [%0], [%1], 16;" :: "r"(dst), "l"(src));
}
__device__ __forceinline__ void mbar_init(unsigned a, unsigned cnt) {
    asm volatile("mbarrier.init.shared.b64 [%0], %1;" :: "r"(a), "r"(cnt) : "memory");
}
__device__ __forceinline__ void mbar_arrive(unsigned a) {
    asm volatile("mbarrier.arrive.shared.b64 _, [%0];" :: "r"(a) : "memory");
}
// arrive when ALL of this thread's prior cp.asyncs have completed
__device__ __forceinline__ void cp_mbar_arrive(unsigned a) {
    asm volatile("cp.async.mbarrier.arrive.noinc.shared.b64 [%0];" :: "r"(a) : "memory");
}
__device__ __forceinline__ void mbar_wait(unsigned mbar, unsigned phase) {
    asm volatile(
        "{\n\t.reg .pred P1;\n\t"
        "WL%=:\n\t"
        "mbarrier.try_wait.parity.acquire.cta.shared::cta.b64 P1, [%0], %1, 0x989680;\n\t"
        "@P1 bra.uni WD%=;\n\t"
        "bra.uni WL%=;\n\t"
        "WD%=:\n\t}"
        :: "r"(mbar), "r"(phase) : "memory");
}

// ---------------------------------------------------------------------------
// Projection on tensor cores (unchanged; ~4us)
// ---------------------------------------------------------------------------
__global__ __launch_bounds__(256) void proj_mma_kernel(
    const float* __restrict__ x, const float* __restrict__ xx,
    const float* __restrict__ Wq, const float* __restrict__ Wk,
    const float* __restrict__ Wv)
{
    __shared__ __align__(16) char sm[128 * 72 * 2 + 64 * 136 * 2];
    __half* As = (__half*)sm;
    __half* Bs = (__half*)(sm + 128 * 72 * 2);
    __half* St = (__half*)sm;

    const int which = blockIdx.z / BATCH;
    const int b     = blockIdx.z % BATCH;
    const float* __restrict__ in = (which == 0) ? x : xx;
    const float* __restrict__ W  = (which == 0) ? Wq : ((which == 1) ? Wk : Wv);

    const int n0   = blockIdx.x * 128;
    const int o0   = blockIdx.y * 128;
    const int tid  = threadIdx.x;
    const int lane = tid & 31;
    const int warp = tid >> 5;
    const int g    = lane >> 2;
    const int tq   = lane & 3;
    const int wr   = warp >> 1;
    const int wcn  = warp & 1;

    const unsigned ab = (unsigned)__cvta_generic_to_shared(As);
    const unsigned bb = (unsigned)__cvta_generic_to_shared(Bs);

    float4 acc[2][8];
    #pragma unroll
    for (int mt = 0; mt < 2; mt++)
        #pragma unroll
        for (int j = 0; j < 8; j++) acc[mt][j] = make_float4(0.f, 0.f, 0.f, 0.f);

    for (int c0 = 0; c0 < CIN; c0 += 64) {
        __syncthreads();
        for (int t = tid; t < 128 * 16; t += 256) {
            int r = t >> 4, cc = (t & 15) * 4;
            float4 w = *(const float4*)&W[(o0 + r) * CIN + c0 + cc];
            half2* d = (half2*)&As[r * 72 + cc];
            d[0] = __floats2half2_rn(w.x, w.y);
            d[1] = __floats2half2_rn(w.z, w.w);
        }
        for (int t = tid; t < 64 * 32; t += 256) {
            int r = t >> 5, nn = (t & 31) * 4;
            float4 v = *(const float4*)&in[((size_t)b * CIN + c0 + r) * NPTS + n0 + nn];
            half2* d = (half2*)&Bs[r * 136 + nn];
            d[0] = __floats2half2_rn(v.x, v.y);
            d[1] = __floats2half2_rn(v.z, v.w);
        }
        __syncthreads();

        #pragma unroll
        for (int s = 0; s < 4; s++) {
            unsigned a[2][4];
            #pragma unroll
            for (int mt = 0; mt < 2; mt++)
                ldsm_x4(a[mt][0], a[mt][1], a[mt][2], a[mt][3],
                        ab + ((32 * wr + 16 * mt + (lane & 15)) * 72
                              + (lane >> 4) * 8 + 16 * s) * 2);
            #pragma unroll
            for (int ntp = 0; ntp < 4; ntp++) {
                unsigned b0, b1, b2, b3;
                ldsm_x4_t(b0, b1, b2, b3,
                          bb + ((16 * s + (lane & 15)) * 136
                                + 64 * wcn + 16 * ntp + 8 * (lane >> 4)) * 2);
                #pragma unroll
                for (int mt = 0; mt < 2; mt++) {
                    mma16816(acc[mt][2 * ntp],     a[mt][0], a[mt][1], a[mt][2], a[mt][3], b0, b1);
                    mma16816(acc[mt][2 * ntp + 1], a[mt][0], a[mt][1], a[mt][2], a[mt][3], b2, b3);
                }
            }
        }
    }
    __syncthreads();

    if (which == 2) {
        #pragma unroll
        for (int mt = 0; mt < 2; mt++)
            #pragma unroll
            for (int j = 0; j < 8; j++) {
                int o_ = 32 * wr + 16 * mt + g;
                int n_ = 64 * wcn + 8 * j + 2 * tq;
                *(half2*)&St[o_ * 136 + n_]       = __floats2half2_rn(acc[mt][j].x, acc[mt][j].y);
                *(half2*)&St[(o_ + 8) * 136 + n_] = __floats2half2_rn(acc[mt][j].z, acc[mt][j].w);
            }
        __syncthreads();
        for (int t = tid; t < 128 * 16; t += 256) {
            int r = t >> 4, nn = (t & 15) * 8;
            *(uint4*)&g_vt[((size_t)b * OUTC + o0 + r) * NPTS + n0 + nn] =
                *(uint4*)&St[r * 136 + nn];
        }
    } else {
        const float sc = (which == 0) ? QSCALE : 1.0f;
        __half* base = (which == 0) ? g_qh : g_kh;
        #pragma unroll
        for (int mt = 0; mt < 2; mt++)
            #pragma unroll
            for (int j = 0; j < 8; j++) {
                int o_ = 32 * wr + 16 * mt + g;
                int n_ = 64 * wcn + 8 * j + 2 * tq;
                St[n_ * 136 + o_]           = __float2half_rn(acc[mt][j].x * sc);
                St[(n_ + 1) * 136 + o_]     = __float2half_rn(acc[mt][j].y * sc);
                St[n_ * 136 + o_ + 8]       = __float2half_rn(acc[mt][j].z * sc);
                St[(n_ + 1) * 136 + o_ + 8] = __float2half_rn(acc[mt][j].w * sc);
            }
        __syncthreads();
        for (int t = tid; t < 128 * 16; t += 256) {
            int r = t >> 4, oc = (t & 15) * 8;
            *(uint4*)&base[((size_t)(b * NPTS) + n0 + r) * OUTC + o0 + oc] =
                *(uint4*)&St[r * 136 + oc];
        }
    }
}

// ---------------------------------------------------------------------------
// Flash attention v6: v5 + mbarrier ring pipeline (no per-tile __syncthreads).
// full[s]: 256 cp.async-completion arrivals (data ready).
// empty[s]: 256 arrivals after each thread's last smem read of the slot.
// Phases derived from t: full wait phase = (t>>1)&1; empty wait (fill u>=2)
// phase = ((u>>1)+1)&1. Warps proceed with up to ~1 tile of skew.
// ---------------------------------------------------------------------------
#define KBUF_HALF (64 * 264)
#define VBUF_HALF (256 * 72)

struct AttnSmem6 {
    __half Qs[128 * 264];     // 67584 B
    __half Ks[2][KBUF_HALF];  // 2 x 33792 B
    __half Vs[2][VBUF_HALF];  // 2 x 36864 B
    unsigned long long mb[4]; // full0, full1, empty0, empty1
};                            // 208928 B -> 1 CTA/SM
// Epilogue overlays float O[256][132] (135168 B) on Qs/Ks/Vs (mb untouched).

__global__ __launch_bounds__(256, 1) void attn_kernel6(float* __restrict__ out)
{
    extern __shared__ char smraw[];
    AttnSmem6& S = *reinterpret_cast<AttnSmem6*>(smraw);

    const int tid  = threadIdx.x;
    const int lane = tid & 31;
    const int w    = tid >> 5;
    const int g    = lane >> 2;
    const int tq   = lane & 3;
    const int b    = blockIdx.y;
    const int n0   = blockIdx.x * 128;

    const __half* __restrict__ Qh = g_qh + (size_t)b * NPTS * OUTC;
    const __half* __restrict__ Kh = g_kh + (size_t)b * NPTS * OUTC;
    const __half* __restrict__ Vt = g_vt + (size_t)b * OUTC * NPTS;

    const unsigned qb = (unsigned)__cvta_generic_to_shared(S.Qs);
    const unsigned kb = (unsigned)__cvta_generic_to_shared(S.Ks[0]);
    const unsigned vb = (unsigned)__cvta_generic_to_shared(S.Vs[0]);
    const unsigned mb = (unsigned)__cvta_generic_to_shared(S.mb);

    // ---- init barriers ----
    if (tid == 0) {
        mbar_init(mb + 0, 256);   // full[0]
        mbar_init(mb + 8, 256);   // full[1]
        mbar_init(mb + 16, 256);  // empty[0]
        mbar_init(mb + 24, 256);  // empty[1]
    }
    __syncthreads();

    // ---- prologue: Q (persistent) + K/V tile 0; full[0] tracks completion ----
    #pragma unroll
    for (int i = 0; i < 16; i++) {
        int idx = tid + i * 256;
        int r = idx >> 5, c = idx & 31;
        cp16(qb + (r * 264 + c * 8) * 2, &Qh[(size_t)(n0 + r) * OUTC + c * 8]);
    }
    #pragma unroll
    for (int i = 0; i < 8; i++) {
        int idx = tid + i * 256;
        int r = idx >> 5, c = idx & 31;
        cp16(kb + (r * 264 + c * 8) * 2, &Kh[(size_t)r * OUTC + c * 8]);
        int d = idx >> 3, c2 = idx & 7;
        cp16(vb + (d * 72 + c2 * 8) * 2, &Vt[(size_t)d * NPTS + c2 * 8]);
    }
    cp_mbar_arrive(mb + 0);

    const unsigned aQ  = qb + ((16 * w + (lane & 15)) * 264 + (lane >> 4) * 8) * 2;
    const unsigned bK0 = kb + (((lane & 7) + 8 * (lane >> 4)) * 264
                               + ((lane >> 3) & 1) * 8) * 2;
    const unsigned bV0 = vb + (((lane & 7) + 8 * (lane >> 4)) * 72
                               + ((lane >> 3) & 1) * 8) * 2;

    float l0 = 0.f, l1 = 0.f;
    float4 oacc[32];
    #pragma unroll
    for (int i = 0; i < 32; i++) oacc[i] = make_float4(0.f, 0.f, 0.f, 0.f);

    for (int t = 0; t < NT; t++) {
        const int buf = t & 1;

        // ---- data ready for tile t? ----
        mbar_wait(mb + 8 * buf, (unsigned)((t >> 1) & 1));

        // ---- S = Q K^T : warp computes 16 rows x 64 keys ----
        float4 sacc[8];
        #pragma unroll
        for (int nt = 0; nt < 8; nt++) sacc[nt] = make_float4(0.f, 0.f, 0.f, 0.f);

        const unsigned kB = bK0 + buf * (KBUF_HALF * 2);
        #pragma unroll
        for (int s = 0; s < 16; s++) {
            unsigned a0, a1, a2, a3;
            ldsm_x4(a0, a1, a2, a3, aQ + s * 32);
            #pragma unroll
            for (int kt = 0; kt < 4; kt++) {
                unsigned b0, b1, b2, b3;
                ldsm_x4(b0, b1, b2, b3, kB + kt * 8448 + s * 32);
                mma16816(sacc[2 * kt],     a0, a1, a2, a3, b0, b1);
                mma16816(sacc[2 * kt + 1], a0, a1, a2, a3, b2, b3);
            }
        }

        // ---- produce tile t+1 into the other slot ----
        if (t + 1 < NT) {
            const int u = t + 1;
            const int sb1 = u & 1;
            if (u >= 2)
                mbar_wait(mb + 16 + 8 * sb1, (unsigned)(((u >> 1) + 1) & 1));
            const int k0n = u * 64;
            const unsigned kN = kb + sb1 * (KBUF_HALF * 2);
            const unsigned vN = vb + sb1 * (VBUF_HALF * 2);
            #pragma unroll
            for (int i = 0; i < 8; i++) {
                int idx = tid + i * 256;
                int r = idx >> 5, c = idx & 31;
                cp16(kN + (r * 264 + c * 8) * 2,
                     &Kh[(size_t)(k0n + r) * OUTC + c * 8]);
                int d = idx >> 3, c2 = idx & 7;
                cp16(vN + (d * 72 + c2 * 8) * 2,
                     &Vt[(size_t)d * NPTS + k0n + c2 * 8]);
            }
            cp_mbar_arrive(mb + 8 * sb1);
        }

        const unsigned vB = bV0 + buf * (VBUF_HALF * 2);
        unsigned pa[16];

        // ---- exp (keys 0-31): ex2 (log2e folded into Q) ----
        #pragma unroll
        for (int s = 0; s < 2; s++) {
            float x0 = ex2(sacc[2 * s].x),     y0 = ex2(sacc[2 * s].y);
            float z0 = ex2(sacc[2 * s].z),     w0 = ex2(sacc[2 * s].w);
            float x1 = ex2(sacc[2 * s + 1].x), y1 = ex2(sacc[2 * s + 1].y);
            float z1 = ex2(sacc[2 * s + 1].z), w1 = ex2(sacc[2 * s + 1].w);
            l0 += x0 + y0 + x1 + y1;
            l1 += z0 + w0 + z1 + w1;
            pa[4 * s + 0] = pack_f16x2(x0, y0);
            pa[4 * s + 1] = pack_f16x2(z0, w0);
            pa[4 * s + 2] = pack_f16x2(x1, y1);
            pa[4 * s + 3] = pack_f16x2(z1, w1);
        }

        // ---- PV step 0 overlaps exp of keys 32-63 ----
        #pragma unroll
        for (int vt = 0; vt < 16; vt++) {
            unsigned b0, b1, b2, b3;
            ldsm_x4(b0, b1, b2, b3, vB + vt * 2304);
            mma16816(oacc[2 * vt],     pa[0], pa[1], pa[2], pa[3], b0, b1);
            mma16816(oacc[2 * vt + 1], pa[0], pa[1], pa[2], pa[3], b2, b3);
        }

        // ---- exp (keys 32-63) ----
        #pragma unroll
        for (int s = 2; s < 4; s++) {
            float x0 = ex2(sacc[2 * s].x),     y0 = ex2(sacc[2 * s].y);
            float z0 = ex2(sacc[2 * s].z),     w0 = ex2(sacc[2 * s].w);
            float x1 = ex2(sacc[2 * s + 1].x), y1 = ex2(sacc[2 * s + 1].y);
            float z1 = ex2(sacc[2 * s + 1].z), w1 = ex2(sacc[2 * s + 1].w);
            l0 += x0 + y0 + x1 + y1;
            l1 += z0 + w0 + z1 + w1;
            pa[4 * s + 0] = pack_f16x2(x0, y0);
            pa[4 * s + 1] = pack_f16x2(z0, w0);
            pa[4 * s + 2] = pack_f16x2(x1, y1);
            pa[4 * s + 3] = pack_f16x2(z1, w1);
        }

        // ---- PV steps 1-3 ----
        #pragma unroll
        for (int s = 1; s < 4; s++) {
            #pragma unroll
            for (int vt = 0; vt < 16; vt++) {
                unsigned b0, b1, b2, b3;
                ldsm_x4(b0, b1, b2, b3, vB + vt * 2304 + s * 32);
                mma16816(oacc[2 * vt],     pa[4 * s], pa[4 * s + 1], pa[4 * s + 2], pa[4 * s + 3], b0, b1);
                mma16816(oacc[2 * vt + 1], pa[4 * s], pa[4 * s + 1], pa[4 * s + 2], pa[4 * s + 3], b2, b3);
            }
        }

        // ---- done reading slot buf for tile t ----
        mbar_arrive(mb + 16 + 8 * buf);
    }

    // ---- lane-reduce l ----
    #pragma unroll
    for (int mk = 1; mk <= 2; mk <<= 1) {
        l0 += __shfl_xor_sync(0xffffffffu, l0, mk);
        l1 += __shfl_xor_sync(0xffffffffu, l1, mk);
    }
    const float inv0 = 1.0f / l0;
    const float inv1 = 1.0f / l1;

    // ---- epilogue: stage O in smem as [col][n], then float4 STG ----
    float* Osm = (float*)smraw;
    __syncthreads();   // all warps past the loop; smem reusable
    {
        const int rA = 16 * w + g;
        const int rB = rA + 8;
        #pragma unroll
        for (int dt = 0; dt < 32; dt++) {
            int col = 8 * dt + 2 * tq;
            Osm[(col)     * 132 + rA] = oacc[dt].x * inv0;
            Osm[(col + 1) * 132 + rA] = oacc[dt].y * inv0;
            Osm[(col)     * 132 + rB] = oacc[dt].z * inv1;
            Osm[(col + 1) * 132 + rB] = oacc[dt].w * inv1;
        }
    }
    __syncthreads();
    #pragma unroll
    for (int cc = 0; cc < 32; cc++) {
        int col = cc * 8 + w;
        int n = 4 * lane;
        float4 v = *(float4*)&Osm[col * 132 + n];
        *(float4*)&out[((size_t)b * OUTC + col) * NPTS + n0 + n] = v;
    }
}

// ---------------------------------------------------------------------------
extern "C" void kernel_launch(void* const* d_in, const int* in_sizes, int n_in,
                              void* d_out, int out_size)
{
    const float* x  = (const float*)d_in[0];
    const float* xx = (const float*)d_in[1];
    const float* Wq = (const float*)d_in[2];
    const float* Wk = (const float*)d_in[3];
    const float* Wv = (const float*)d_in[4];
    float* out = (float*)d_out;

    cudaFuncSetAttribute(attn_kernel6, cudaFuncAttributeMaxDynamicSharedMemorySize,
                         (int)sizeof(AttnSmem6));

    proj_mma_kernel<<<dim3(NPTS / 128, OUTC / 128, 3 * BATCH), 256>>>(x, xx, Wq, Wk, Wv);
    attn_kernel6<<<dim3(NPTS / 128, BATCH), 256, sizeof(AttnSmem6)>>>(out);
}